// round 1
// baseline (speedup 1.0000x reference)
#include <cuda_runtime.h>
#include <math.h>

#define NN 100000
#define EE 1600000
#define HH 4
#define HIDD 64
#define FD 256   // H*HID == IN == FC

// ---------------- scratch (device globals; no allocations anywhere) ----------
__device__ float g_ht[(size_t)NN * FD];   // pre-aggregation features / feat
__device__ float g_h [(size_t)NN * FD];   // post-aggregation features (h1 / h2)
__device__ float g_a1[HH * NN];
__device__ float g_a2[HH * NN];
__device__ float g_s [(size_t)HH * EE];   // edge softmax numerators per head
__device__ int   g_cnt[NN];
__device__ int   g_cur[NN];
__device__ int   g_incl[NN];
__device__ int   g_rowptr[NN + 1];
__device__ int   g_bsum[128];
__device__ int   g_boff[128];
__device__ int   g_ssrc[EE];
__device__ int   g_sdst[EE];

// ---------------- CSR build ---------------------------------------------------
__global__ void k_zero_counts() {
    int i = blockIdx.x * blockDim.x + threadIdx.x;
    if (i < NN) { g_cnt[i] = 0; g_cur[i] = 0; }
}

__global__ void k_hist(const int* __restrict__ src) {
    int e = blockIdx.x * blockDim.x + threadIdx.x;
    if (e < EE) atomicAdd(&g_cnt[src[e]], 1);
}

__global__ void k_scan_block() {
    __shared__ int sh[1024];
    int tid = threadIdx.x;
    int i = blockIdx.x * 1024 + tid;
    int v = (i < NN) ? g_cnt[i] : 0;
    sh[tid] = v;
    __syncthreads();
    for (int off = 1; off < 1024; off <<= 1) {
        int t = (tid >= off) ? sh[tid - off] : 0;
        __syncthreads();
        sh[tid] += t;
        __syncthreads();
    }
    if (i < NN) g_incl[i] = sh[tid];
    if (tid == 1023) g_bsum[blockIdx.x] = sh[1023];
}

__global__ void k_scan_top(int nb) {
    int run = 0;
    for (int b = 0; b < nb; b++) { g_boff[b] = run; run += g_bsum[b]; }
}

__global__ void k_rowptr() {
    int i = blockIdx.x * blockDim.x + threadIdx.x;
    if (i < NN) g_rowptr[i] = g_boff[i >> 10] + g_incl[i] - g_cnt[i];
    if (i == 0) g_rowptr[NN] = EE;
}

__global__ void k_scatter(const int* __restrict__ src, const int* __restrict__ dst) {
    int e = blockIdx.x * blockDim.x + threadIdx.x;
    if (e >= EE) return;
    int u = src[e];
    int pos = g_rowptr[u] + atomicAdd(&g_cur[u], 1);
    g_ssrc[pos] = u;
    g_sdst[pos] = dst[e];
}

// ---------------- SGEMM: C[M,256] = A[M,256] * B[256,256]^T (+bias, relu) -----
__global__ __launch_bounds__(256, 2)
void k_sgemm_nt(const float* __restrict__ A, const float* __restrict__ B,
                float* __restrict__ C, int M,
                const float* __restrict__ bias, int relu) {
    const int K = 256;
    __shared__ float As[8][128];
    __shared__ float Bs[8][128];
    int tid  = threadIdx.x;
    int row0 = blockIdx.y * 128;
    int col0 = blockIdx.x * 128;
    int lr = tid >> 1;          // 0..127
    int lk = (tid & 1) * 4;     // 0 or 4

    float acc[8][8];
#pragma unroll
    for (int i = 0; i < 8; i++)
#pragma unroll
        for (int j = 0; j < 8; j++) acc[i][j] = 0.f;

    const float* Aptr = A + (size_t)(row0 + lr) * K + lk;
    const float* Bptr = B + (size_t)(col0 + lr) * K + lk;
    bool aok = (row0 + lr) < M;

    int m0 = (tid >> 4) * 8;
    int n0 = (tid & 15) * 8;

    for (int k0 = 0; k0 < K; k0 += 8) {
        float4 av = aok ? *(const float4*)(Aptr + k0) : make_float4(0.f, 0.f, 0.f, 0.f);
        float4 bv = *(const float4*)(Bptr + k0);
        As[lk + 0][lr] = av.x; As[lk + 1][lr] = av.y;
        As[lk + 2][lr] = av.z; As[lk + 3][lr] = av.w;
        Bs[lk + 0][lr] = bv.x; Bs[lk + 1][lr] = bv.y;
        Bs[lk + 2][lr] = bv.z; Bs[lk + 3][lr] = bv.w;
        __syncthreads();
#pragma unroll
        for (int k = 0; k < 8; k++) {
            float4 a0 = *(const float4*)&As[k][m0];
            float4 a1 = *(const float4*)&As[k][m0 + 4];
            float4 b0 = *(const float4*)&Bs[k][n0];
            float4 b1 = *(const float4*)&Bs[k][n0 + 4];
            float a[8] = {a0.x, a0.y, a0.z, a0.w, a1.x, a1.y, a1.z, a1.w};
            float b[8] = {b0.x, b0.y, b0.z, b0.w, b1.x, b1.y, b1.z, b1.w};
#pragma unroll
            for (int i = 0; i < 8; i++)
#pragma unroll
                for (int j = 0; j < 8; j++) acc[i][j] += a[i] * b[j];
        }
        __syncthreads();
    }

#pragma unroll
    for (int i = 0; i < 8; i++) {
        int row = row0 + m0 + i;
        if (row >= M) continue;
#pragma unroll
        for (int j = 0; j < 8; j++) {
            int col = col0 + n0 + j;
            float v = acc[i][j];
            if (bias) v += bias[col];
            if (relu) v = fmaxf(v, 0.f);
            C[(size_t)row * 256 + col] = v;
        }
    }
}

// ---------------- per-node attention scalars ---------------------------------
__global__ void k_scores(const float* __restrict__ ht,
                         const float* __restrict__ a1w, const float* __restrict__ a1b,
                         const float* __restrict__ a2w, const float* __restrict__ a2b) {
    int gw = (blockIdx.x * blockDim.x + threadIdx.x) >> 5;
    int lane = threadIdx.x & 31;
    if (gw >= NN * HH) return;
    int i = gw & 3;
    int n = gw >> 2;
    const float* hr = ht + (size_t)n * FD + i * HIDD;
    float v0 = hr[lane], v1 = hr[lane + 32];
    float p1 = v0 * a1w[i * HIDD + lane] + v1 * a1w[i * HIDD + lane + 32];
    float p2 = v0 * a2w[i * HIDD + lane] + v1 * a2w[i * HIDD + lane + 32];
#pragma unroll
    for (int off = 16; off; off >>= 1) {
        p1 += __shfl_down_sync(0xffffffffu, p1, off);
        p2 += __shfl_down_sync(0xffffffffu, p2, off);
    }
    if (lane == 0) {
        g_a1[i * NN + n] = p1 + a1b[i];
        g_a2[i * NN + n] = p2 + a2b[i];
    }
}

// ---------------- edge softmax numerators ------------------------------------
__global__ void k_edge_s() {
    int e = blockIdx.x * blockDim.x + threadIdx.x;
    if (e >= EE) return;
    int u = g_ssrc[e], v = g_sdst[e];
#pragma unroll
    for (int i = 0; i < HH; i++) {
        float z = g_a1[i * NN + u] + g_a2[i * NN + v];
        z = z > 0.f ? z : 0.2f * z;
        g_s[(size_t)i * EE + e] = expf(z);
    }
}

// ---------------- aggregation: warp per (node, head) --------------------------
__global__ void k_agg(const float* __restrict__ ht, const float* __restrict__ b,
                      float* __restrict__ out, int relu) {
    int n = blockIdx.x;
    int i = threadIdx.x >> 5;
    int lane = threadIdx.x & 31;
    int s0 = g_rowptr[n], s1 = g_rowptr[n + 1];
    const float* sp = g_s + (size_t)i * EE;
    float acc0 = 0.f, acc1 = 0.f, den = 0.f;
    for (int e = s0; e < s1; e++) {
        int d = g_sdst[e];
        float w = sp[e];
        den += w;
        const float* hr = ht + (size_t)d * FD + i * HIDD;
        acc0 += w * hr[lane];
        acc1 += w * hr[lane + 32];
    }
    float inv = 1.f / den;
    float o0 = acc0 * inv + b[i * HIDD + lane];
    float o1 = acc1 * inv + b[i * HIDD + lane + 32];
    if (relu) { o0 = fmaxf(o0, 0.f); o1 = fmaxf(o1, 0.f); }
    out[(size_t)n * FD + i * HIDD + lane]      = o0;
    out[(size_t)n * FD + i * HIDD + lane + 32] = o1;
}

// ---------------- classifier: [N,256] x [4,256]^T + bias ----------------------
__global__ void k_cls(const float* __restrict__ feat, const float* __restrict__ W,
                      const float* __restrict__ bias, float* __restrict__ out) {
    __shared__ float w[1024];
    int tid = threadIdx.x;
#pragma unroll
    for (int j = 0; j < 4; j++) w[tid + 256 * j] = W[tid + 256 * j];
    __syncthreads();
    int warp = tid >> 5, lane = tid & 31;
    int n = blockIdx.x * 8 + warp;
    if (n >= NN) return;
    const float* f = feat + (size_t)n * 256;
    float p0 = 0.f, p1 = 0.f, p2 = 0.f, p3 = 0.f;
#pragma unroll
    for (int k = lane; k < 256; k += 32) {
        float x = f[k];
        p0 += x * w[k];
        p1 += x * w[256 + k];
        p2 += x * w[512 + k];
        p3 += x * w[768 + k];
    }
#pragma unroll
    for (int off = 16; off; off >>= 1) {
        p0 += __shfl_down_sync(0xffffffffu, p0, off);
        p1 += __shfl_down_sync(0xffffffffu, p1, off);
        p2 += __shfl_down_sync(0xffffffffu, p2, off);
        p3 += __shfl_down_sync(0xffffffffu, p3, off);
    }
    if (lane == 0) {
        out[(size_t)n * 4 + 0] = p0 + bias[0];
        out[(size_t)n * 4 + 1] = p1 + bias[1];
        out[(size_t)n * 4 + 2] = p2 + bias[2];
        out[(size_t)n * 4 + 3] = p3 + bias[3];
    }
}

// ---------------- launch -------------------------------------------------------
extern "C" void kernel_launch(void* const* d_in, const int* in_sizes, int n_in,
                              void* d_out, int out_size) {
    const float* x    = (const float*)d_in[0];
    const int*   ei   = (const int*)  d_in[1];
    const float* W1   = (const float*)d_in[2];
    const float* a11w = (const float*)d_in[3];
    const float* a11b = (const float*)d_in[4];
    const float* a12w = (const float*)d_in[5];
    const float* a12b = (const float*)d_in[6];
    const float* b1   = (const float*)d_in[7];
    const float* W2   = (const float*)d_in[8];
    const float* a21w = (const float*)d_in[9];
    const float* a21b = (const float*)d_in[10];
    const float* a22w = (const float*)d_in[11];
    const float* a22b = (const float*)d_in[12];
    const float* b2   = (const float*)d_in[13];
    const float* Wc   = (const float*)d_in[14];
    const float* bc   = (const float*)d_in[15];
    const float* Wcls = (const float*)d_in[16];
    const float* bcls = (const float*)d_in[17];
    float* out = (float*)d_out;

    const int* srcp = ei;
    const int* dstp = ei + EE;

    float *ht = nullptr, *h = nullptr;
    cudaGetSymbolAddress((void**)&ht, g_ht);
    cudaGetSymbolAddress((void**)&h,  g_h);

    int tE = (EE + 255) / 256;
    int tN = (NN + 255) / 256;
    int nScanBlocks = (NN + 1023) / 1024;

    // CSR build (by src)
    k_zero_counts<<<tN, 256>>>();
    k_hist<<<tE, 256>>>(srcp);
    k_scan_block<<<nScanBlocks, 1024>>>();
    k_scan_top<<<1, 1>>>(nScanBlocks);
    k_rowptr<<<tN, 256>>>();
    k_scatter<<<tE, 256>>>(srcp, dstp);

    dim3 gg(2, (NN + 127) / 128);
    int scoreBlocks = (NN * HH + 7) / 8;   // 8 warps / block

    // ---- layer 1 ----
    k_sgemm_nt<<<gg, 256>>>(x, W1, ht, NN, nullptr, 0);
    k_scores<<<scoreBlocks, 256>>>(ht, a11w, a11b, a12w, a12b);
    k_edge_s<<<tE, 256>>>();
    k_agg<<<NN, 128>>>(ht, b1, h, 1);          // h = relu(h1)

    // ---- layer 2 ----
    k_sgemm_nt<<<gg, 256>>>(h, W2, ht, NN, nullptr, 0);
    k_scores<<<scoreBlocks, 256>>>(ht, a21w, a21b, a22w, a22b);
    k_edge_s<<<tE, 256>>>();
    k_agg<<<NN, 128>>>(ht, b2, h, 0);          // h = h2 (no relu)

    // ---- collator + classifier ----
    k_sgemm_nt<<<gg, 256>>>(h, Wc, ht, NN, bc, 1);   // ht = feat
    k_cls<<<(NN + 7) / 8, 256>>>(ht, Wcls, bcls, out);
}

// round 2
// speedup vs baseline: 1.5482x; 1.5482x over previous
#include <cuda_runtime.h>
#include <math.h>
#include <stdint.h>

#define NN 100000
#define EE 1600000
#define HH 4
#define HIDD 64
#define FD 256   // H*HID == IN == FC

// ---------------- scratch (device globals; no allocations anywhere) ----------
__device__ float g_ht[(size_t)NN * FD];   // pre-aggregation features / feat
__device__ float g_h [(size_t)NN * FD];   // post-aggregation features (h1 / h2)
__device__ float g_a1[HH * NN];
__device__ float g_a2[HH * NN];
__device__ float g_s [(size_t)HH * EE];   // edge softmax numerators per head
__device__ int   g_cnt[NN];
__device__ int   g_cur[NN];
__device__ int   g_incl[NN];
__device__ int   g_rowptr[NN + 1];
__device__ int   g_bsum[128];
__device__ int   g_boff[128];
__device__ int   g_ssrc[EE];
__device__ int   g_sdst[EE];

// ---------------- CSR build ---------------------------------------------------
__global__ void k_zero_counts() {
    int i = blockIdx.x * blockDim.x + threadIdx.x;
    if (i < NN) { g_cnt[i] = 0; g_cur[i] = 0; }
}

__global__ void k_hist(const int* __restrict__ src) {
    int e = blockIdx.x * blockDim.x + threadIdx.x;
    if (e < EE) atomicAdd(&g_cnt[src[e]], 1);
}

__global__ void k_scan_block() {
    __shared__ int sh[1024];
    int tid = threadIdx.x;
    int i = blockIdx.x * 1024 + tid;
    int v = (i < NN) ? g_cnt[i] : 0;
    sh[tid] = v;
    __syncthreads();
    for (int off = 1; off < 1024; off <<= 1) {
        int t = (tid >= off) ? sh[tid - off] : 0;
        __syncthreads();
        sh[tid] += t;
        __syncthreads();
    }
    if (i < NN) g_incl[i] = sh[tid];
    if (tid == 1023) g_bsum[blockIdx.x] = sh[1023];
}

// parallel top-level scan over <=128 block sums (one block, 128 threads)
__global__ void k_scan_top2(int nb) {
    __shared__ int ws[4];
    int t = threadIdx.x;
    int lane = t & 31, w = t >> 5;
    int v = (t < nb) ? g_bsum[t] : 0;
    int s = v;
#pragma unroll
    for (int off = 1; off < 32; off <<= 1) {
        int u = __shfl_up_sync(0xffffffffu, s, off);
        if (lane >= off) s += u;
    }
    if (lane == 31) ws[w] = s;
    __syncthreads();
    int add = 0;
#pragma unroll
    for (int i = 0; i < 4; i++) if (i < w) add += ws[i];
    if (t < nb) g_boff[t] = add + s - v;   // exclusive prefix of block sums
}

__global__ void k_rowptr() {
    int i = blockIdx.x * blockDim.x + threadIdx.x;
    if (i < NN) g_rowptr[i] = g_boff[i >> 10] + g_incl[i] - g_cnt[i];
    if (i == 0) g_rowptr[NN] = EE;
}

__global__ void k_scatter(const int* __restrict__ src, const int* __restrict__ dst) {
    int e = blockIdx.x * blockDim.x + threadIdx.x;
    if (e >= EE) return;
    int u = src[e];
    int pos = g_rowptr[u] + atomicAdd(&g_cur[u], 1);
    g_ssrc[pos] = u;
    g_sdst[pos] = dst[e];
}

// ---------------- TF32 tensor-core GEMM ---------------------------------------
// C[M,256] = A[M,256] * B[256,256]^T  (B row-major [out,in] == col-major K x N)
// Block tile 128x128, BK=16, 8 warps (2 along M x 4 along N), warp tile 64x32.
#define BM 128
#define BN 128
#define BKK 16
#define LDA 136   // BM + 8 pad (stride in words) -> conflict-free frag LDS

__device__ __forceinline__ uint32_t f2tf32(float x) {
    uint32_t r;
    asm("cvt.rna.tf32.f32 %0, %1;" : "=r"(r) : "f"(x));
    return r;
}

__device__ __forceinline__ void mma_tf32(float& d0, float& d1, float& d2, float& d3,
                                         uint32_t a0, uint32_t a1, uint32_t a2, uint32_t a3,
                                         uint32_t b0, uint32_t b1) {
    asm volatile(
        "mma.sync.aligned.m16n8k8.row.col.f32.tf32.tf32.f32 "
        "{%0,%1,%2,%3}, {%4,%5,%6,%7}, {%8,%9}, {%0,%1,%2,%3};\n"
        : "+f"(d0), "+f"(d1), "+f"(d2), "+f"(d3)
        : "r"(a0), "r"(a1), "r"(a2), "r"(a3), "r"(b0), "r"(b1));
}

__global__ __launch_bounds__(256, 2)
void k_gemm_tf32(const float* __restrict__ A, const float* __restrict__ B,
                 float* __restrict__ C, int M,
                 const float* __restrict__ bias, int relu) {
    const int K = 256;
    __shared__ uint32_t As[2][BKK][LDA];
    __shared__ uint32_t Bs[2][BKK][LDA];

    int tid  = threadIdx.x;
    int row0 = blockIdx.y * BM;
    int col0 = blockIdx.x * BN;
    int warp = tid >> 5, lane = tid & 31;
    int wm = (warp & 1) * 64;       // warp row offset within block tile
    int wn = (warp >> 1) * 32;      // warp col offset

    // global load mapping: thread t loads rows lr, lr+64; k-quad kq
    int lr = tid >> 2;              // 0..63
    int kq = (tid & 3) * 4;         // 0,4,8,12

    const float* Ap0 = A + (size_t)(row0 + lr) * K + kq;
    const float* Ap1 = A + (size_t)(row0 + lr + 64) * K + kq;
    const float* Bp0 = B + (size_t)(col0 + lr) * K + kq;
    const float* Bp1 = B + (size_t)(col0 + lr + 64) * K + kq;
    bool aok0 = (row0 + lr) < M;
    bool aok1 = (row0 + lr + 64) < M;

    float acc[4][4][4];
#pragma unroll
    for (int i = 0; i < 4; i++)
#pragma unroll
        for (int j = 0; j < 4; j++)
#pragma unroll
            for (int c = 0; c < 4; c++) acc[i][j][c] = 0.f;

    float4 ra0, ra1, rb0, rb1;
    const float4 z4 = make_float4(0.f, 0.f, 0.f, 0.f);

    // prologue: load tile 0, store to buf 0
    ra0 = aok0 ? *(const float4*)(Ap0) : z4;
    ra1 = aok1 ? *(const float4*)(Ap1) : z4;
    rb0 = *(const float4*)(Bp0);
    rb1 = *(const float4*)(Bp1);
    {
        As[0][kq + 0][lr] = f2tf32(ra0.x); As[0][kq + 1][lr] = f2tf32(ra0.y);
        As[0][kq + 2][lr] = f2tf32(ra0.z); As[0][kq + 3][lr] = f2tf32(ra0.w);
        As[0][kq + 0][lr + 64] = f2tf32(ra1.x); As[0][kq + 1][lr + 64] = f2tf32(ra1.y);
        As[0][kq + 2][lr + 64] = f2tf32(ra1.z); As[0][kq + 3][lr + 64] = f2tf32(ra1.w);
        Bs[0][kq + 0][lr] = f2tf32(rb0.x); Bs[0][kq + 1][lr] = f2tf32(rb0.y);
        Bs[0][kq + 2][lr] = f2tf32(rb0.z); Bs[0][kq + 3][lr] = f2tf32(rb0.w);
        Bs[0][kq + 0][lr + 64] = f2tf32(rb1.x); Bs[0][kq + 1][lr + 64] = f2tf32(rb1.y);
        Bs[0][kq + 2][lr + 64] = f2tf32(rb1.z); Bs[0][kq + 3][lr + 64] = f2tf32(rb1.w);
    }
    __syncthreads();

    const int NIT = K / BKK;   // 16
    int r = lane >> 2;         // 0..7
    int c = lane & 3;          // 0..3

    for (int kt = 0; kt < NIT; kt++) {
        int buf = kt & 1;
        if (kt + 1 < NIT) {
            int k0 = (kt + 1) * BKK;
            ra0 = aok0 ? *(const float4*)(Ap0 + k0) : z4;
            ra1 = aok1 ? *(const float4*)(Ap1 + k0) : z4;
            rb0 = *(const float4*)(Bp0 + k0);
            rb1 = *(const float4*)(Bp1 + k0);
        }

#pragma unroll
        for (int ks = 0; ks < 2; ks++) {
            uint32_t af[4][4];
#pragma unroll
            for (int mt = 0; mt < 4; mt++) {
                int m = wm + mt * 16 + r;
                af[mt][0] = As[buf][ks * 8 + c][m];
                af[mt][1] = As[buf][ks * 8 + c][m + 8];
                af[mt][2] = As[buf][ks * 8 + c + 4][m];
                af[mt][3] = As[buf][ks * 8 + c + 4][m + 8];
            }
            uint32_t bf[4][2];
#pragma unroll
            for (int nt = 0; nt < 4; nt++) {
                int n = wn + nt * 8 + r;
                bf[nt][0] = Bs[buf][ks * 8 + c][n];
                bf[nt][1] = Bs[buf][ks * 8 + c + 4][n];
            }
#pragma unroll
            for (int mt = 0; mt < 4; mt++)
#pragma unroll
                for (int nt = 0; nt < 4; nt++)
                    mma_tf32(acc[mt][nt][0], acc[mt][nt][1], acc[mt][nt][2], acc[mt][nt][3],
                             af[mt][0], af[mt][1], af[mt][2], af[mt][3],
                             bf[nt][0], bf[nt][1]);
        }

        if (kt + 1 < NIT) {
            int nb = buf ^ 1;
            As[nb][kq + 0][lr] = f2tf32(ra0.x); As[nb][kq + 1][lr] = f2tf32(ra0.y);
            As[nb][kq + 2][lr] = f2tf32(ra0.z); As[nb][kq + 3][lr] = f2tf32(ra0.w);
            As[nb][kq + 0][lr + 64] = f2tf32(ra1.x); As[nb][kq + 1][lr + 64] = f2tf32(ra1.y);
            As[nb][kq + 2][lr + 64] = f2tf32(ra1.z); As[nb][kq + 3][lr + 64] = f2tf32(ra1.w);
            Bs[nb][kq + 0][lr] = f2tf32(rb0.x); Bs[nb][kq + 1][lr] = f2tf32(rb0.y);
            Bs[nb][kq + 2][lr] = f2tf32(rb0.z); Bs[nb][kq + 3][lr] = f2tf32(rb0.w);
            Bs[nb][kq + 0][lr + 64] = f2tf32(rb1.x); Bs[nb][kq + 1][lr + 64] = f2tf32(rb1.y);
            Bs[nb][kq + 2][lr + 64] = f2tf32(rb1.z); Bs[nb][kq + 3][lr + 64] = f2tf32(rb1.w);
        }
        __syncthreads();
    }

    // epilogue: C fragment layout -> rows r, r+8; cols 2c, 2c+1
#pragma unroll
    for (int mt = 0; mt < 4; mt++) {
#pragma unroll
        for (int nt = 0; nt < 4; nt++) {
            int col = col0 + wn + nt * 8 + c * 2;
            float bx = 0.f, by = 0.f;
            if (bias) { bx = bias[col]; by = bias[col + 1]; }
            int row_a = row0 + wm + mt * 16 + r;
            int row_b = row_a + 8;
            float v0 = acc[mt][nt][0] + bx, v1 = acc[mt][nt][1] + by;
            float v2 = acc[mt][nt][2] + bx, v3 = acc[mt][nt][3] + by;
            if (relu) {
                v0 = fmaxf(v0, 0.f); v1 = fmaxf(v1, 0.f);
                v2 = fmaxf(v2, 0.f); v3 = fmaxf(v3, 0.f);
            }
            if (row_a < M) *(float2*)&C[(size_t)row_a * 256 + col] = make_float2(v0, v1);
            if (row_b < M) *(float2*)&C[(size_t)row_b * 256 + col] = make_float2(v2, v3);
        }
    }
}

// ---------------- per-node attention scalars ---------------------------------
__global__ void k_scores(const float* __restrict__ ht,
                         const float* __restrict__ a1w, const float* __restrict__ a1b,
                         const float* __restrict__ a2w, const float* __restrict__ a2b) {
    int gw = (blockIdx.x * blockDim.x + threadIdx.x) >> 5;
    int lane = threadIdx.x & 31;
    if (gw >= NN * HH) return;
    int i = gw & 3;
    int n = gw >> 2;
    const float* hr = ht + (size_t)n * FD + i * HIDD;
    float v0 = hr[lane], v1 = hr[lane + 32];
    float p1 = v0 * a1w[i * HIDD + lane] + v1 * a1w[i * HIDD + lane + 32];
    float p2 = v0 * a2w[i * HIDD + lane] + v1 * a2w[i * HIDD + lane + 32];
#pragma unroll
    for (int off = 16; off; off >>= 1) {
        p1 += __shfl_down_sync(0xffffffffu, p1, off);
        p2 += __shfl_down_sync(0xffffffffu, p2, off);
    }
    if (lane == 0) {
        g_a1[i * NN + n] = p1 + a1b[i];
        g_a2[i * NN + n] = p2 + a2b[i];
    }
}

// ---------------- edge softmax numerators ------------------------------------
__global__ void k_edge_s() {
    int e = blockIdx.x * blockDim.x + threadIdx.x;
    if (e >= EE) return;
    int u = g_ssrc[e], v = g_sdst[e];
#pragma unroll
    for (int i = 0; i < HH; i++) {
        float z = g_a1[i * NN + u] + g_a2[i * NN + v];
        z = z > 0.f ? z : 0.2f * z;
        g_s[(size_t)i * EE + e] = expf(z);
    }
}

// ---------------- aggregation: warp per (node, head) --------------------------
__global__ void k_agg(const float* __restrict__ ht, const float* __restrict__ b,
                      float* __restrict__ out, int relu) {
    int n = blockIdx.x;
    int i = threadIdx.x >> 5;
    int lane = threadIdx.x & 31;
    int s0 = g_rowptr[n], s1 = g_rowptr[n + 1];
    const float* sp = g_s + (size_t)i * EE;
    float acc0 = 0.f, acc1 = 0.f, den = 0.f;

    int e = s0;
    int d = 0; float w = 0.f;
    if (e < s1) { d = g_sdst[e]; w = sp[e]; }
    while (e < s1) {
        int   dn = 0;
        float wn = 0.f;
        if (e + 1 < s1) { dn = g_sdst[e + 1]; wn = sp[e + 1]; }
        const float* hr = ht + (size_t)d * FD + i * HIDD;
        den  += w;
        acc0 += w * hr[lane];
        acc1 += w * hr[lane + 32];
        d = dn; w = wn; e++;
    }

    float inv = 1.f / den;
    float o0 = acc0 * inv + b[i * HIDD + lane];
    float o1 = acc1 * inv + b[i * HIDD + lane + 32];
    if (relu) { o0 = fmaxf(o0, 0.f); o1 = fmaxf(o1, 0.f); }
    out[(size_t)n * FD + i * HIDD + lane]      = o0;
    out[(size_t)n * FD + i * HIDD + lane + 32] = o1;
}

// ---------------- classifier: [N,256] x [4,256]^T + bias ----------------------
__global__ void k_cls(const float* __restrict__ feat, const float* __restrict__ W,
                      const float* __restrict__ bias, float* __restrict__ out) {
    __shared__ float w[1024];
    int tid = threadIdx.x;
#pragma unroll
    for (int j = 0; j < 4; j++) w[tid + 256 * j] = W[tid + 256 * j];
    __syncthreads();
    int warp = tid >> 5, lane = tid & 31;
    int n = blockIdx.x * 8 + warp;
    if (n >= NN) return;
    const float* f = feat + (size_t)n * 256;
    float p0 = 0.f, p1 = 0.f, p2 = 0.f, p3 = 0.f;
#pragma unroll
    for (int k = lane; k < 256; k += 32) {
        float x = f[k];
        p0 += x * w[k];
        p1 += x * w[256 + k];
        p2 += x * w[512 + k];
        p3 += x * w[768 + k];
    }
#pragma unroll
    for (int off = 16; off; off >>= 1) {
        p0 += __shfl_down_sync(0xffffffffu, p0, off);
        p1 += __shfl_down_sync(0xffffffffu, p1, off);
        p2 += __shfl_down_sync(0xffffffffu, p2, off);
        p3 += __shfl_down_sync(0xffffffffu, p3, off);
    }
    if (lane == 0) {
        out[(size_t)n * 4 + 0] = p0 + bias[0];
        out[(size_t)n * 4 + 1] = p1 + bias[1];
        out[(size_t)n * 4 + 2] = p2 + bias[2];
        out[(size_t)n * 4 + 3] = p3 + bias[3];
    }
}

// ---------------- launch -------------------------------------------------------
extern "C" void kernel_launch(void* const* d_in, const int* in_sizes, int n_in,
                              void* d_out, int out_size) {
    const float* x    = (const float*)d_in[0];
    const int*   ei   = (const int*)  d_in[1];
    const float* W1   = (const float*)d_in[2];
    const float* a11w = (const float*)d_in[3];
    const float* a11b = (const float*)d_in[4];
    const float* a12w = (const float*)d_in[5];
    const float* a12b = (const float*)d_in[6];
    const float* b1   = (const float*)d_in[7];
    const float* W2   = (const float*)d_in[8];
    const float* a21w = (const float*)d_in[9];
    const float* a21b = (const float*)d_in[10];
    const float* a22w = (const float*)d_in[11];
    const float* a22b = (const float*)d_in[12];
    const float* b2   = (const float*)d_in[13];
    const float* Wc   = (const float*)d_in[14];
    const float* bc   = (const float*)d_in[15];
    const float* Wcls = (const float*)d_in[16];
    const float* bcls = (const float*)d_in[17];
    float* out = (float*)d_out;

    const int* srcp = ei;
    const int* dstp = ei + EE;

    float *ht = nullptr, *h = nullptr;
    cudaGetSymbolAddress((void**)&ht, g_ht);
    cudaGetSymbolAddress((void**)&h,  g_h);

    int tE = (EE + 255) / 256;
    int tN = (NN + 255) / 256;
    int nScanBlocks = (NN + 1023) / 1024;

    // CSR build (by src)
    k_zero_counts<<<tN, 256>>>();
    k_hist<<<tE, 256>>>(srcp);
    k_scan_block<<<nScanBlocks, 1024>>>();
    k_scan_top2<<<1, 128>>>(nScanBlocks);
    k_rowptr<<<tN, 256>>>();
    k_scatter<<<tE, 256>>>(srcp, dstp);

    dim3 gg(2, (NN + 127) / 128);
    int scoreBlocks = (NN * HH + 7) / 8;   // 8 warps / block

    // ---- layer 1 ----
    k_gemm_tf32<<<gg, 256>>>(x, W1, ht, NN, nullptr, 0);
    k_scores<<<scoreBlocks, 256>>>(ht, a11w, a11b, a12w, a12b);
    k_edge_s<<<tE, 256>>>();
    k_agg<<<NN, 128>>>(ht, b1, h, 1);          // h = relu(h1)

    // ---- layer 2 ----
    k_gemm_tf32<<<gg, 256>>>(h, W2, ht, NN, nullptr, 0);
    k_scores<<<scoreBlocks, 256>>>(ht, a21w, a21b, a22w, a22b);
    k_edge_s<<<tE, 256>>>();
    k_agg<<<NN, 128>>>(ht, b2, h, 0);          // h = h2 (no relu)

    // ---- collator + classifier ----
    k_gemm_tf32<<<gg, 256>>>(h, Wc, ht, NN, bc, 1);   // ht = feat
    k_cls<<<(NN + 7) / 8, 256>>>(ht, Wcls, bcls, out);
}

// round 3
// speedup vs baseline: 1.9002x; 1.2274x over previous
#include <cuda_runtime.h>
#include <cuda_fp16.h>
#include <math.h>
#include <stdint.h>

#define NN 100000
#define EE 1600000
#define HH 4
#define HIDD 64
#define FD 256   // H*HID == IN == FC

// ---------------- scratch (device globals; no allocations anywhere) ----------
__device__ float  g_ht[(size_t)NN * FD];   // pre-aggregation features / feat (fp32)
__device__ __half g_hth[(size_t)NN * FD];  // fp16 copy for the agg gather
__device__ float  g_h [(size_t)NN * FD];   // post-aggregation features (h1 / h2)
__device__ float  g_a1[HH * NN];
__device__ float  g_a2[HH * NN];
__device__ int    g_cnt[NN];
__device__ int    g_cur[NN];
__device__ int    g_incl[NN];
__device__ int    g_rowptr[NN + 1];
__device__ int    g_bsum[128];
__device__ int    g_boff[128];
__device__ int    g_sdst[EE];

// ---------------- CSR build ---------------------------------------------------
__global__ void k_zero_counts() {
    int i = blockIdx.x * blockDim.x + threadIdx.x;
    if (i < NN) { g_cnt[i] = 0; g_cur[i] = 0; }
}

__global__ void k_hist(const int* __restrict__ src) {
    int e = blockIdx.x * blockDim.x + threadIdx.x;
    if (e < EE) atomicAdd(&g_cnt[src[e]], 1);
}

__global__ void k_scan_block() {
    __shared__ int sh[1024];
    int tid = threadIdx.x;
    int i = blockIdx.x * 1024 + tid;
    int v = (i < NN) ? g_cnt[i] : 0;
    sh[tid] = v;
    __syncthreads();
    for (int off = 1; off < 1024; off <<= 1) {
        int t = (tid >= off) ? sh[tid - off] : 0;
        __syncthreads();
        sh[tid] += t;
        __syncthreads();
    }
    if (i < NN) g_incl[i] = sh[tid];
    if (tid == 1023) g_bsum[blockIdx.x] = sh[1023];
}

// parallel top-level scan over <=128 block sums (one block, 128 threads)
__global__ void k_scan_top2(int nb) {
    __shared__ int ws[4];
    int t = threadIdx.x;
    int lane = t & 31, w = t >> 5;
    int v = (t < nb) ? g_bsum[t] : 0;
    int s = v;
#pragma unroll
    for (int off = 1; off < 32; off <<= 1) {
        int u = __shfl_up_sync(0xffffffffu, s, off);
        if (lane >= off) s += u;
    }
    if (lane == 31) ws[w] = s;
    __syncthreads();
    int add = 0;
#pragma unroll
    for (int i = 0; i < 4; i++) if (i < w) add += ws[i];
    if (t < nb) g_boff[t] = add + s - v;   // exclusive prefix of block sums
}

__global__ void k_rowptr() {
    int i = blockIdx.x * blockDim.x + threadIdx.x;
    if (i < NN) g_rowptr[i] = g_boff[i >> 10] + g_incl[i] - g_cnt[i];
    if (i == 0) g_rowptr[NN] = EE;
}

__global__ void k_scatter(const int* __restrict__ src, const int* __restrict__ dst) {
    int e = blockIdx.x * blockDim.x + threadIdx.x;
    if (e >= EE) return;
    int u = src[e];
    int pos = g_rowptr[u] + atomicAdd(&g_cur[u], 1);
    g_sdst[pos] = dst[e];
}

// ---------------- TF32 tensor-core GEMM ---------------------------------------
// C[M,256] = A[M,256] * B[256,256]^T  (B row-major [out,in] == col-major K x N)
// Block tile 128x128, BK=16, 8 warps (2 along M x 4 along N), warp tile 64x32.
#define BM 128
#define BN 128
#define BKK 16
#define LDA 136   // BM + 8 pad (stride in words) -> conflict-free frag LDS

__device__ __forceinline__ uint32_t f2tf32(float x) {
    uint32_t r;
    asm("cvt.rna.tf32.f32 %0, %1;" : "=r"(r) : "f"(x));
    return r;
}

__device__ __forceinline__ void mma_tf32(float& d0, float& d1, float& d2, float& d3,
                                         uint32_t a0, uint32_t a1, uint32_t a2, uint32_t a3,
                                         uint32_t b0, uint32_t b1) {
    asm volatile(
        "mma.sync.aligned.m16n8k8.row.col.f32.tf32.tf32.f32 "
        "{%0,%1,%2,%3}, {%4,%5,%6,%7}, {%8,%9}, {%0,%1,%2,%3};\n"
        : "+f"(d0), "+f"(d1), "+f"(d2), "+f"(d3)
        : "r"(a0), "r"(a1), "r"(a2), "r"(a3), "r"(b0), "r"(b1));
}

__global__ __launch_bounds__(256, 2)
void k_gemm_tf32(const float* __restrict__ A, const float* __restrict__ B,
                 float* __restrict__ C, __half* __restrict__ Ch, int M,
                 const float* __restrict__ bias, int relu) {
    const int K = 256;
    __shared__ uint32_t As[2][BKK][LDA];
    __shared__ uint32_t Bs[2][BKK][LDA];

    int tid  = threadIdx.x;
    int row0 = blockIdx.y * BM;
    int col0 = blockIdx.x * BN;
    int warp = tid >> 5, lane = tid & 31;
    int wm = (warp & 1) * 64;       // warp row offset within block tile
    int wn = (warp >> 1) * 32;      // warp col offset

    int lr = tid >> 2;              // 0..63
    int kq = (tid & 3) * 4;         // 0,4,8,12

    const float* Ap0 = A + (size_t)(row0 + lr) * K + kq;
    const float* Ap1 = A + (size_t)(row0 + lr + 64) * K + kq;
    const float* Bp0 = B + (size_t)(col0 + lr) * K + kq;
    const float* Bp1 = B + (size_t)(col0 + lr + 64) * K + kq;
    bool aok0 = (row0 + lr) < M;
    bool aok1 = (row0 + lr + 64) < M;

    float acc[4][4][4];
#pragma unroll
    for (int i = 0; i < 4; i++)
#pragma unroll
        for (int j = 0; j < 4; j++)
#pragma unroll
            for (int c = 0; c < 4; c++) acc[i][j][c] = 0.f;

    float4 ra0, ra1, rb0, rb1;
    const float4 z4 = make_float4(0.f, 0.f, 0.f, 0.f);

    ra0 = aok0 ? *(const float4*)(Ap0) : z4;
    ra1 = aok1 ? *(const float4*)(Ap1) : z4;
    rb0 = *(const float4*)(Bp0);
    rb1 = *(const float4*)(Bp1);
    {
        As[0][kq + 0][lr] = f2tf32(ra0.x); As[0][kq + 1][lr] = f2tf32(ra0.y);
        As[0][kq + 2][lr] = f2tf32(ra0.z); As[0][kq + 3][lr] = f2tf32(ra0.w);
        As[0][kq + 0][lr + 64] = f2tf32(ra1.x); As[0][kq + 1][lr + 64] = f2tf32(ra1.y);
        As[0][kq + 2][lr + 64] = f2tf32(ra1.z); As[0][kq + 3][lr + 64] = f2tf32(ra1.w);
        Bs[0][kq + 0][lr] = f2tf32(rb0.x); Bs[0][kq + 1][lr] = f2tf32(rb0.y);
        Bs[0][kq + 2][lr] = f2tf32(rb0.z); Bs[0][kq + 3][lr] = f2tf32(rb0.w);
        Bs[0][kq + 0][lr + 64] = f2tf32(rb1.x); Bs[0][kq + 1][lr + 64] = f2tf32(rb1.y);
        Bs[0][kq + 2][lr + 64] = f2tf32(rb1.z); Bs[0][kq + 3][lr + 64] = f2tf32(rb1.w);
    }
    __syncthreads();

    const int NIT = K / BKK;   // 16
    int r = lane >> 2;         // 0..7
    int c = lane & 3;          // 0..3

    for (int kt = 0; kt < NIT; kt++) {
        int buf = kt & 1;
        if (kt + 1 < NIT) {
            int k0 = (kt + 1) * BKK;
            ra0 = aok0 ? *(const float4*)(Ap0 + k0) : z4;
            ra1 = aok1 ? *(const float4*)(Ap1 + k0) : z4;
            rb0 = *(const float4*)(Bp0 + k0);
            rb1 = *(const float4*)(Bp1 + k0);
        }

#pragma unroll
        for (int ks = 0; ks < 2; ks++) {
            uint32_t af[4][4];
#pragma unroll
            for (int mt = 0; mt < 4; mt++) {
                int m = wm + mt * 16 + r;
                af[mt][0] = As[buf][ks * 8 + c][m];
                af[mt][1] = As[buf][ks * 8 + c][m + 8];
                af[mt][2] = As[buf][ks * 8 + c + 4][m];
                af[mt][3] = As[buf][ks * 8 + c + 4][m + 8];
            }
            uint32_t bf[4][2];
#pragma unroll
            for (int nt = 0; nt < 4; nt++) {
                int n = wn + nt * 8 + r;
                bf[nt][0] = Bs[buf][ks * 8 + c][n];
                bf[nt][1] = Bs[buf][ks * 8 + c + 4][n];
            }
#pragma unroll
            for (int mt = 0; mt < 4; mt++)
#pragma unroll
                for (int nt = 0; nt < 4; nt++)
                    mma_tf32(acc[mt][nt][0], acc[mt][nt][1], acc[mt][nt][2], acc[mt][nt][3],
                             af[mt][0], af[mt][1], af[mt][2], af[mt][3],
                             bf[nt][0], bf[nt][1]);
        }

        if (kt + 1 < NIT) {
            int nb = buf ^ 1;
            As[nb][kq + 0][lr] = f2tf32(ra0.x); As[nb][kq + 1][lr] = f2tf32(ra0.y);
            As[nb][kq + 2][lr] = f2tf32(ra0.z); As[nb][kq + 3][lr] = f2tf32(ra0.w);
            As[nb][kq + 0][lr + 64] = f2tf32(ra1.x); As[nb][kq + 1][lr + 64] = f2tf32(ra1.y);
            As[nb][kq + 2][lr + 64] = f2tf32(ra1.z); As[nb][kq + 3][lr + 64] = f2tf32(ra1.w);
            Bs[nb][kq + 0][lr] = f2tf32(rb0.x); Bs[nb][kq + 1][lr] = f2tf32(rb0.y);
            Bs[nb][kq + 2][lr] = f2tf32(rb0.z); Bs[nb][kq + 3][lr] = f2tf32(rb0.w);
            Bs[nb][kq + 0][lr + 64] = f2tf32(rb1.x); Bs[nb][kq + 1][lr + 64] = f2tf32(rb1.y);
            Bs[nb][kq + 2][lr + 64] = f2tf32(rb1.z); Bs[nb][kq + 3][lr + 64] = f2tf32(rb1.w);
        }
        __syncthreads();
    }

    // epilogue: rows r, r+8; cols 2c, 2c+1 per (mt, nt)
#pragma unroll
    for (int mt = 0; mt < 4; mt++) {
#pragma unroll
        for (int nt = 0; nt < 4; nt++) {
            int col = col0 + wn + nt * 8 + c * 2;
            float bx = 0.f, by = 0.f;
            if (bias) { bx = bias[col]; by = bias[col + 1]; }
            int row_a = row0 + wm + mt * 16 + r;
            int row_b = row_a + 8;
            float v0 = acc[mt][nt][0] + bx, v1 = acc[mt][nt][1] + by;
            float v2 = acc[mt][nt][2] + bx, v3 = acc[mt][nt][3] + by;
            if (relu) {
                v0 = fmaxf(v0, 0.f); v1 = fmaxf(v1, 0.f);
                v2 = fmaxf(v2, 0.f); v3 = fmaxf(v3, 0.f);
            }
            if (row_a < M) {
                *(float2*)&C[(size_t)row_a * 256 + col] = make_float2(v0, v1);
                if (Ch) *(__half2*)&Ch[(size_t)row_a * 256 + col] = __floats2half2_rn(v0, v1);
            }
            if (row_b < M) {
                *(float2*)&C[(size_t)row_b * 256 + col] = make_float2(v2, v3);
                if (Ch) *(__half2*)&Ch[(size_t)row_b * 256 + col] = __floats2half2_rn(v2, v3);
            }
        }
    }
}

// ---------------- per-node attention scalars ---------------------------------
__global__ void k_scores(const float* __restrict__ ht,
                         const float* __restrict__ a1w, const float* __restrict__ a1b,
                         const float* __restrict__ a2w, const float* __restrict__ a2b) {
    int gw = (blockIdx.x * blockDim.x + threadIdx.x) >> 5;
    int lane = threadIdx.x & 31;
    if (gw >= NN * HH) return;
    int i = gw & 3;
    int n = gw >> 2;
    const float* hr = ht + (size_t)n * FD + i * HIDD;
    float v0 = hr[lane], v1 = hr[lane + 32];
    float p1 = v0 * a1w[i * HIDD + lane] + v1 * a1w[i * HIDD + lane + 32];
    float p2 = v0 * a2w[i * HIDD + lane] + v1 * a2w[i * HIDD + lane + 32];
#pragma unroll
    for (int off = 16; off; off >>= 1) {
        p1 += __shfl_down_sync(0xffffffffu, p1, off);
        p2 += __shfl_down_sync(0xffffffffu, p2, off);
    }
    if (lane == 0) {
        g_a1[i * NN + n] = p1 + a1b[i];
        g_a2[i * NN + n] = p2 + a2b[i];
    }
}

// ---------------- fused edge softmax + aggregation ----------------------------
// warp per (node, head): chunk of 32 edges -> lane-parallel weight computation
// (gather a2[dst], leaky-relu, exp), then shfl-broadcast into the channel-
// parallel fp16 gather loop. lane owns channels 2*lane, 2*lane+1.
__global__ __launch_bounds__(128, 8)
void k_agg(const __half* __restrict__ hth, const float* __restrict__ b,
           float* __restrict__ out, int relu) {
    int n = blockIdx.x;
    int i = threadIdx.x >> 5;
    int lane = threadIdx.x & 31;
    int s0 = g_rowptr[n], s1 = g_rowptr[n + 1];
    float a1u = g_a1[i * NN + n];
    const float* a2p = g_a2 + (size_t)i * NN;

    float acc0 = 0.f, acc1 = 0.f, den = 0.f;

    for (int base = s0; base < s1; base += 32) {
        int m = s1 - base;
        int cnt = m < 32 ? m : 32;
        int d = 0; float w = 0.f;
        if (lane < cnt) {
            d = g_sdst[base + lane];
            float z = a1u + a2p[d];
            z = z > 0.f ? z : 0.2f * z;
            w = __expf(z);
        }
        for (int j = 0; j < cnt; j++) {
            float wj = __shfl_sync(0xffffffffu, w, j);
            int   dj = __shfl_sync(0xffffffffu, d, j);
            const __half2* hr = (const __half2*)(hth + (size_t)dj * FD + i * HIDD);
            float2 vf = __half22float2(hr[lane]);
            den  += wj;
            acc0 += wj * vf.x;
            acc1 += wj * vf.y;
        }
    }

    float inv = 1.f / den;
    int ch = i * HIDD + 2 * lane;
    float o0 = acc0 * inv + b[ch];
    float o1 = acc1 * inv + b[ch + 1];
    if (relu) { o0 = fmaxf(o0, 0.f); o1 = fmaxf(o1, 0.f); }
    *(float2*)&out[(size_t)n * FD + ch] = make_float2(o0, o1);
}

// ---------------- classifier: [N,256] x [4,256]^T + bias ----------------------
__global__ void k_cls(const float* __restrict__ feat, const float* __restrict__ W,
                      const float* __restrict__ bias, float* __restrict__ out) {
    __shared__ float w[1024];
    int tid = threadIdx.x;
#pragma unroll
    for (int j = 0; j < 4; j++) w[tid + 256 * j] = W[tid + 256 * j];
    __syncthreads();
    int warp = tid >> 5, lane = tid & 31;
    int n = blockIdx.x * 8 + warp;
    if (n >= NN) return;
    const float* f = feat + (size_t)n * 256;
    float p0 = 0.f, p1 = 0.f, p2 = 0.f, p3 = 0.f;
#pragma unroll
    for (int k = lane; k < 256; k += 32) {
        float x = f[k];
        p0 += x * w[k];
        p1 += x * w[256 + k];
        p2 += x * w[512 + k];
        p3 += x * w[768 + k];
    }
#pragma unroll
    for (int off = 16; off; off >>= 1) {
        p0 += __shfl_down_sync(0xffffffffu, p0, off);
        p1 += __shfl_down_sync(0xffffffffu, p1, off);
        p2 += __shfl_down_sync(0xffffffffu, p2, off);
        p3 += __shfl_down_sync(0xffffffffu, p3, off);
    }
    if (lane == 0) {
        out[(size_t)n * 4 + 0] = p0 + bias[0];
        out[(size_t)n * 4 + 1] = p1 + bias[1];
        out[(size_t)n * 4 + 2] = p2 + bias[2];
        out[(size_t)n * 4 + 3] = p3 + bias[3];
    }
}

// ---------------- launch -------------------------------------------------------
extern "C" void kernel_launch(void* const* d_in, const int* in_sizes, int n_in,
                              void* d_out, int out_size) {
    const float* x    = (const float*)d_in[0];
    const int*   ei   = (const int*)  d_in[1];
    const float* W1   = (const float*)d_in[2];
    const float* a11w = (const float*)d_in[3];
    const float* a11b = (const float*)d_in[4];
    const float* a12w = (const float*)d_in[5];
    const float* a12b = (const float*)d_in[6];
    const float* b1   = (const float*)d_in[7];
    const float* W2   = (const float*)d_in[8];
    const float* a21w = (const float*)d_in[9];
    const float* a21b = (const float*)d_in[10];
    const float* a22w = (const float*)d_in[11];
    const float* a22b = (const float*)d_in[12];
    const float* b2   = (const float*)d_in[13];
    const float* Wc   = (const float*)d_in[14];
    const float* bc   = (const float*)d_in[15];
    const float* Wcls = (const float*)d_in[16];
    const float* bcls = (const float*)d_in[17];
    float* out = (float*)d_out;

    const int* srcp = ei;
    const int* dstp = ei + EE;

    float *ht = nullptr, *h = nullptr;
    __half* hth = nullptr;
    cudaGetSymbolAddress((void**)&ht,  g_ht);
    cudaGetSymbolAddress((void**)&h,   g_h);
    cudaGetSymbolAddress((void**)&hth, g_hth);

    int tE = (EE + 255) / 256;
    int tN = (NN + 255) / 256;
    int nScanBlocks = (NN + 1023) / 1024;

    // CSR build (by src); only dst is materialized per slot
    k_zero_counts<<<tN, 256>>>();
    k_hist<<<tE, 256>>>(srcp);
    k_scan_block<<<nScanBlocks, 1024>>>();
    k_scan_top2<<<1, 128>>>(nScanBlocks);
    k_rowptr<<<tN, 256>>>();
    k_scatter<<<tE, 256>>>(srcp, dstp);

    dim3 gg(2, (NN + 127) / 128);
    int scoreBlocks = (NN * HH + 7) / 8;   // 8 warps / block

    // ---- layer 1 ----
    k_gemm_tf32<<<gg, 256>>>(x, W1, ht, hth, NN, nullptr, 0);
    k_scores<<<scoreBlocks, 256>>>(ht, a11w, a11b, a12w, a12b);
    k_agg<<<NN, 128>>>(hth, b1, h, 1);          // h = relu(h1)

    // ---- layer 2 ----
    k_gemm_tf32<<<gg, 256>>>(h, W2, ht, hth, NN, nullptr, 0);
    k_scores<<<scoreBlocks, 256>>>(ht, a21w, a21b, a22w, a22b);
    k_agg<<<NN, 128>>>(hth, b2, h, 0);          // h = h2 (no relu)

    // ---- collator + classifier ----
    k_gemm_tf32<<<gg, 256>>>(h, Wc, ht, nullptr, NN, bc, 1);   // ht = feat
    k_cls<<<(NN + 7) / 8, 256>>>(ht, Wcls, bcls, out);
}

// round 4
// speedup vs baseline: 2.0605x; 1.0843x over previous
#include <cuda_runtime.h>
#include <cuda_fp16.h>
#include <math.h>
#include <stdint.h>

#define NN 100000
#define EE 1600000
#define HH 4
#define HIDD 64
#define FD 256   // H*HID == IN == FC

// ---------------- scratch (device globals; no allocations anywhere) ----------
__device__ __half g_hth[(size_t)NN * FD];  // GEMM outputs (ht / feat), fp16
__device__ __half g_hh [(size_t)NN * FD];  // agg outputs (h1 / h2), fp16
__device__ float  g_a1[HH * NN];
__device__ float  g_a2[HH * NN];
__device__ int    g_cnt[NN];
__device__ int    g_cur[NN];
__device__ int    g_incl[NN];
__device__ int    g_rowptr[NN + 1];
__device__ int    g_bsum[128];
__device__ int    g_boff[128];
__device__ int    g_sdst[EE];

// ---------------- CSR build ---------------------------------------------------
__global__ void k_zero_counts() {
    int i = blockIdx.x * blockDim.x + threadIdx.x;
    if (i < NN) { g_cnt[i] = 0; g_cur[i] = 0; }
}

__global__ void k_hist(const int* __restrict__ src) {
    int e = blockIdx.x * blockDim.x + threadIdx.x;
    if (e < EE) atomicAdd(&g_cnt[src[e]], 1);
}

__global__ void k_scan_block() {
    __shared__ int sh[1024];
    int tid = threadIdx.x;
    int i = blockIdx.x * 1024 + tid;
    int v = (i < NN) ? g_cnt[i] : 0;
    sh[tid] = v;
    __syncthreads();
    for (int off = 1; off < 1024; off <<= 1) {
        int t = (tid >= off) ? sh[tid - off] : 0;
        __syncthreads();
        sh[tid] += t;
        __syncthreads();
    }
    if (i < NN) g_incl[i] = sh[tid];
    if (tid == 1023) g_bsum[blockIdx.x] = sh[1023];
}

__global__ void k_scan_top2(int nb) {
    __shared__ int ws[4];
    int t = threadIdx.x;
    int lane = t & 31, w = t >> 5;
    int v = (t < nb) ? g_bsum[t] : 0;
    int s = v;
#pragma unroll
    for (int off = 1; off < 32; off <<= 1) {
        int u = __shfl_up_sync(0xffffffffu, s, off);
        if (lane >= off) s += u;
    }
    if (lane == 31) ws[w] = s;
    __syncthreads();
    int add = 0;
#pragma unroll
    for (int i = 0; i < 4; i++) if (i < w) add += ws[i];
    if (t < nb) g_boff[t] = add + s - v;
}

__global__ void k_rowptr() {
    int i = blockIdx.x * blockDim.x + threadIdx.x;
    if (i < NN) g_rowptr[i] = g_boff[i >> 10] + g_incl[i] - g_cnt[i];
    if (i == 0) g_rowptr[NN] = EE;
}

__global__ void k_scatter(const int* __restrict__ src, const int* __restrict__ dst) {
    int e = blockIdx.x * blockDim.x + threadIdx.x;
    if (e >= EE) return;
    int u = src[e];
    int pos = g_rowptr[u] + atomicAdd(&g_cur[u], 1);
    g_sdst[pos] = dst[e];
}

// ---------------- TF32 tensor-core GEMM ---------------------------------------
// C[M,256] = A[M,256] * B[256,256]^T; A fp32 or fp16 (template), C fp16 only.
#define BM 128
#define BN 128
#define BKK 16
#define LDA 136   // BM + 8 pad words -> conflict-free frag LDS

__device__ __forceinline__ uint32_t f2tf32(float x) {
    uint32_t r;
    asm("cvt.rna.tf32.f32 %0, %1;" : "=r"(r) : "f"(x));
    return r;
}

__device__ __forceinline__ void mma_tf32(float& d0, float& d1, float& d2, float& d3,
                                         uint32_t a0, uint32_t a1, uint32_t a2, uint32_t a3,
                                         uint32_t b0, uint32_t b1) {
    asm volatile(
        "mma.sync.aligned.m16n8k8.row.col.f32.tf32.tf32.f32 "
        "{%0,%1,%2,%3}, {%4,%5,%6,%7}, {%8,%9}, {%0,%1,%2,%3};\n"
        : "+f"(d0), "+f"(d1), "+f"(d2), "+f"(d3)
        : "r"(a0), "r"(a1), "r"(a2), "r"(a3), "r"(b0), "r"(b1));
}

template<int AHALF>
__global__ __launch_bounds__(256, 2)
void k_gemm(const void* __restrict__ Ain, const float* __restrict__ B,
            __half* __restrict__ Ch, int M,
            const float* __restrict__ bias, int relu) {
    const int K = 256;
    __shared__ uint32_t As[2][BKK][LDA];
    __shared__ uint32_t Bs[2][BKK][LDA];

    const float*  Af = (const float*)Ain;
    const __half* Ah = (const __half*)Ain;

    int tid  = threadIdx.x;
    int row0 = blockIdx.y * BM;
    int col0 = blockIdx.x * BN;
    int warp = tid >> 5, lane = tid & 31;
    int wm = (warp & 1) * 64;
    int wn = (warp >> 1) * 32;

    int lr = tid >> 2;              // 0..63
    int kq = (tid & 3) * 4;         // 0,4,8,12

    size_t aoff0 = (size_t)(row0 + lr) * K + kq;
    size_t aoff1 = (size_t)(row0 + lr + 64) * K + kq;
    const float* Bp0 = B + (size_t)(col0 + lr) * K + kq;
    const float* Bp1 = B + (size_t)(col0 + lr + 64) * K + kq;
    bool aok0 = (row0 + lr) < M;
    bool aok1 = (row0 + lr + 64) < M;

    const float4 z4 = make_float4(0.f, 0.f, 0.f, 0.f);

    auto loadA = [&](size_t off, bool ok) -> float4 {
        if (!ok) return z4;
        if (AHALF) {
            uint2 u = *(const uint2*)(Ah + off);
            float2 f0 = __half22float2(*(__half2*)&u.x);
            float2 f1 = __half22float2(*(__half2*)&u.y);
            return make_float4(f0.x, f0.y, f1.x, f1.y);
        } else {
            return *(const float4*)(Af + off);
        }
    };

    float acc[4][4][4];
#pragma unroll
    for (int i = 0; i < 4; i++)
#pragma unroll
        for (int j = 0; j < 4; j++)
#pragma unroll
            for (int c = 0; c < 4; c++) acc[i][j][c] = 0.f;

    float4 ra0, ra1, rb0, rb1;

    ra0 = loadA(aoff0, aok0);
    ra1 = loadA(aoff1, aok1);
    rb0 = *(const float4*)(Bp0);
    rb1 = *(const float4*)(Bp1);
    {
        As[0][kq + 0][lr] = f2tf32(ra0.x); As[0][kq + 1][lr] = f2tf32(ra0.y);
        As[0][kq + 2][lr] = f2tf32(ra0.z); As[0][kq + 3][lr] = f2tf32(ra0.w);
        As[0][kq + 0][lr + 64] = f2tf32(ra1.x); As[0][kq + 1][lr + 64] = f2tf32(ra1.y);
        As[0][kq + 2][lr + 64] = f2tf32(ra1.z); As[0][kq + 3][lr + 64] = f2tf32(ra1.w);
        Bs[0][kq + 0][lr] = f2tf32(rb0.x); Bs[0][kq + 1][lr] = f2tf32(rb0.y);
        Bs[0][kq + 2][lr] = f2tf32(rb0.z); Bs[0][kq + 3][lr] = f2tf32(rb0.w);
        Bs[0][kq + 0][lr + 64] = f2tf32(rb1.x); Bs[0][kq + 1][lr + 64] = f2tf32(rb1.y);
        Bs[0][kq + 2][lr + 64] = f2tf32(rb1.z); Bs[0][kq + 3][lr + 64] = f2tf32(rb1.w);
    }
    __syncthreads();

    const int NIT = K / BKK;   // 16
    int r = lane >> 2;
    int c = lane & 3;

    for (int kt = 0; kt < NIT; kt++) {
        int buf = kt & 1;
        if (kt + 1 < NIT) {
            int k0 = (kt + 1) * BKK;
            ra0 = loadA(aoff0 + k0, aok0);
            ra1 = loadA(aoff1 + k0, aok1);
            rb0 = *(const float4*)(Bp0 + k0);
            rb1 = *(const float4*)(Bp1 + k0);
        }

#pragma unroll
        for (int ks = 0; ks < 2; ks++) {
            uint32_t af[4][4];
#pragma unroll
            for (int mt = 0; mt < 4; mt++) {
                int m = wm + mt * 16 + r;
                af[mt][0] = As[buf][ks * 8 + c][m];
                af[mt][1] = As[buf][ks * 8 + c][m + 8];
                af[mt][2] = As[buf][ks * 8 + c + 4][m];
                af[mt][3] = As[buf][ks * 8 + c + 4][m + 8];
            }
            uint32_t bf[4][2];
#pragma unroll
            for (int nt = 0; nt < 4; nt++) {
                int n = wn + nt * 8 + r;
                bf[nt][0] = Bs[buf][ks * 8 + c][n];
                bf[nt][1] = Bs[buf][ks * 8 + c + 4][n];
            }
#pragma unroll
            for (int mt = 0; mt < 4; mt++)
#pragma unroll
                for (int nt = 0; nt < 4; nt++)
                    mma_tf32(acc[mt][nt][0], acc[mt][nt][1], acc[mt][nt][2], acc[mt][nt][3],
                             af[mt][0], af[mt][1], af[mt][2], af[mt][3],
                             bf[nt][0], bf[nt][1]);
        }

        if (kt + 1 < NIT) {
            int nb = buf ^ 1;
            As[nb][kq + 0][lr] = f2tf32(ra0.x); As[nb][kq + 1][lr] = f2tf32(ra0.y);
            As[nb][kq + 2][lr] = f2tf32(ra0.z); As[nb][kq + 3][lr] = f2tf32(ra0.w);
            As[nb][kq + 0][lr + 64] = f2tf32(ra1.x); As[nb][kq + 1][lr + 64] = f2tf32(ra1.y);
            As[nb][kq + 2][lr + 64] = f2tf32(ra1.z); As[nb][kq + 3][lr + 64] = f2tf32(ra1.w);
            Bs[nb][kq + 0][lr] = f2tf32(rb0.x); Bs[nb][kq + 1][lr] = f2tf32(rb0.y);
            Bs[nb][kq + 2][lr] = f2tf32(rb0.z); Bs[nb][kq + 3][lr] = f2tf32(rb0.w);
            Bs[nb][kq + 0][lr + 64] = f2tf32(rb1.x); Bs[nb][kq + 1][lr + 64] = f2tf32(rb1.y);
            Bs[nb][kq + 2][lr + 64] = f2tf32(rb1.z); Bs[nb][kq + 3][lr + 64] = f2tf32(rb1.w);
        }
        __syncthreads();
    }

    // epilogue: rows r, r+8; cols 2c, 2c+1 per (mt, nt); fp16 output only
#pragma unroll
    for (int mt = 0; mt < 4; mt++) {
#pragma unroll
        for (int nt = 0; nt < 4; nt++) {
            int col = col0 + wn + nt * 8 + c * 2;
            float bx = 0.f, by = 0.f;
            if (bias) { bx = bias[col]; by = bias[col + 1]; }
            int row_a = row0 + wm + mt * 16 + r;
            int row_b = row_a + 8;
            float v0 = acc[mt][nt][0] + bx, v1 = acc[mt][nt][1] + by;
            float v2 = acc[mt][nt][2] + bx, v3 = acc[mt][nt][3] + by;
            if (relu) {
                v0 = fmaxf(v0, 0.f); v1 = fmaxf(v1, 0.f);
                v2 = fmaxf(v2, 0.f); v3 = fmaxf(v3, 0.f);
            }
            if (row_a < M) *(__half2*)&Ch[(size_t)row_a * 256 + col] = __floats2half2_rn(v0, v1);
            if (row_b < M) *(__half2*)&Ch[(size_t)row_b * 256 + col] = __floats2half2_rn(v2, v3);
        }
    }
}

// ---------------- per-node attention scalars (fp16 input) ---------------------
__global__ void k_scores(const __half* __restrict__ ht,
                         const float* __restrict__ a1w, const float* __restrict__ a1b,
                         const float* __restrict__ a2w, const float* __restrict__ a2b) {
    int gw = (blockIdx.x * blockDim.x + threadIdx.x) >> 5;
    int lane = threadIdx.x & 31;
    if (gw >= NN * HH) return;
    int i = gw & 3;
    int n = gw >> 2;
    const __half2* hr = (const __half2*)(ht + (size_t)n * FD + i * HIDD);
    float2 v = __half22float2(hr[lane]);
    int ch = i * HIDD + 2 * lane;
    float p1 = v.x * a1w[ch] + v.y * a1w[ch + 1];
    float p2 = v.x * a2w[ch] + v.y * a2w[ch + 1];
#pragma unroll
    for (int off = 16; off; off >>= 1) {
        p1 += __shfl_down_sync(0xffffffffu, p1, off);
        p2 += __shfl_down_sync(0xffffffffu, p2, off);
    }
    if (lane == 0) {
        g_a1[i * NN + n] = p1 + a1b[i];
        g_a2[i * NN + n] = p2 + a2b[i];
    }
}

// ---------------- fused edge softmax + aggregation (fp16 in/out) --------------
__global__ __launch_bounds__(128, 8)
void k_agg(const __half* __restrict__ hth, const float* __restrict__ b,
           __half* __restrict__ out, int relu) {
    int n = blockIdx.x;
    int i = threadIdx.x >> 5;
    int lane = threadIdx.x & 31;
    int s0 = g_rowptr[n], s1 = g_rowptr[n + 1];
    float a1u = g_a1[i * NN + n];
    const float* a2p = g_a2 + (size_t)i * NN;

    float acc0 = 0.f, acc1 = 0.f, den = 0.f;

    for (int base = s0; base < s1; base += 32) {
        int m = s1 - base;
        int cnt = m < 32 ? m : 32;
        int d = 0; float w = 0.f;
        if (lane < cnt) {
            d = g_sdst[base + lane];
            float z = a1u + a2p[d];
            z = z > 0.f ? z : 0.2f * z;
            w = __expf(z);
        }
        for (int j = 0; j < cnt; j++) {
            float wj = __shfl_sync(0xffffffffu, w, j);
            int   dj = __shfl_sync(0xffffffffu, d, j);
            const __half2* hr = (const __half2*)(hth + (size_t)dj * FD + i * HIDD);
            float2 vf = __half22float2(hr[lane]);
            den  += wj;
            acc0 += wj * vf.x;
            acc1 += wj * vf.y;
        }
    }

    float inv = 1.f / den;
    int ch = i * HIDD + 2 * lane;
    float o0 = acc0 * inv + b[ch];
    float o1 = acc1 * inv + b[ch + 1];
    if (relu) { o0 = fmaxf(o0, 0.f); o1 = fmaxf(o1, 0.f); }
    *(__half2*)&out[(size_t)n * FD + ch] = __floats2half2_rn(o0, o1);
}

// ---------------- classifier: [N,256](fp16) x [4,256]^T + bias ----------------
__global__ void k_cls(const __half* __restrict__ feat, const float* __restrict__ W,
                      const float* __restrict__ bias, float* __restrict__ out) {
    __shared__ float w[1024];
    int tid = threadIdx.x;
#pragma unroll
    for (int j = 0; j < 4; j++) w[tid + 256 * j] = W[tid + 256 * j];
    __syncthreads();
    int warp = tid >> 5, lane = tid & 31;
    int n = blockIdx.x * 8 + warp;
    if (n >= NN) return;
    const __half2* f = (const __half2*)(feat + (size_t)n * 256);
    float p0 = 0.f, p1 = 0.f, p2 = 0.f, p3 = 0.f;
#pragma unroll
    for (int k = lane; k < 128; k += 32) {
        float2 x = __half22float2(f[k]);
        int c0 = 2 * k, c1 = 2 * k + 1;
        p0 += x.x * w[c0]       + x.y * w[c1];
        p1 += x.x * w[256 + c0] + x.y * w[256 + c1];
        p2 += x.x * w[512 + c0] + x.y * w[512 + c1];
        p3 += x.x * w[768 + c0] + x.y * w[768 + c1];
    }
#pragma unroll
    for (int off = 16; off; off >>= 1) {
        p0 += __shfl_down_sync(0xffffffffu, p0, off);
        p1 += __shfl_down_sync(0xffffffffu, p1, off);
        p2 += __shfl_down_sync(0xffffffffu, p2, off);
        p3 += __shfl_down_sync(0xffffffffu, p3, off);
    }
    if (lane == 0) {
        out[(size_t)n * 4 + 0] = p0 + bias[0];
        out[(size_t)n * 4 + 1] = p1 + bias[1];
        out[(size_t)n * 4 + 2] = p2 + bias[2];
        out[(size_t)n * 4 + 3] = p3 + bias[3];
    }
}

// ---------------- launch -------------------------------------------------------
extern "C" void kernel_launch(void* const* d_in, const int* in_sizes, int n_in,
                              void* d_out, int out_size) {
    const float* x    = (const float*)d_in[0];
    const int*   ei   = (const int*)  d_in[1];
    const float* W1   = (const float*)d_in[2];
    const float* a11w = (const float*)d_in[3];
    const float* a11b = (const float*)d_in[4];
    const float* a12w = (const float*)d_in[5];
    const float* a12b = (const float*)d_in[6];
    const float* b1   = (const float*)d_in[7];
    const float* W2   = (const float*)d_in[8];
    const float* a21w = (const float*)d_in[9];
    const float* a21b = (const float*)d_in[10];
    const float* a22w = (const float*)d_in[11];
    const float* a22b = (const float*)d_in[12];
    const float* b2   = (const float*)d_in[13];
    const float* Wc   = (const float*)d_in[14];
    const float* bc   = (const float*)d_in[15];
    const float* Wcls = (const float*)d_in[16];
    const float* bcls = (const float*)d_in[17];
    float* out = (float*)d_out;

    const int* srcp = ei;
    const int* dstp = ei + EE;

    __half *hth = nullptr, *hh = nullptr;
    cudaGetSymbolAddress((void**)&hth, g_hth);
    cudaGetSymbolAddress((void**)&hh,  g_hh);

    int tE = (EE + 255) / 256;
    int tN = (NN + 255) / 256;
    int nScanBlocks = (NN + 1023) / 1024;

    dim3 gg(2, (NN + 127) / 128);
    int scoreBlocks = (NN * HH + 7) / 8;

    // CSR build interleaved with GEMM1 (independent); GEMM1 sits at launch
    // index 3 so the ncu window (-s 5 -c 1) captures it.
    k_zero_counts<<<tN, 256>>>();
    k_hist<<<tE, 256>>>(srcp);
    k_scan_block<<<nScanBlocks, 1024>>>();
    k_gemm<0><<<gg, 256>>>(x, W1, hth, NN, nullptr, 0);       // profiled slot
    k_scan_top2<<<1, 128>>>(nScanBlocks);
    k_rowptr<<<tN, 256>>>();
    k_scatter<<<tE, 256>>>(srcp, dstp);

    // ---- layer 1 ----
    k_scores<<<scoreBlocks, 256>>>(hth, a11w, a11b, a12w, a12b);
    k_agg<<<NN, 128>>>(hth, b1, hh, 1);           // hh = relu(h1), fp16

    // ---- layer 2 ----
    k_gemm<1><<<gg, 256>>>(hh, W2, hth, NN, nullptr, 0);
    k_scores<<<scoreBlocks, 256>>>(hth, a21w, a21b, a22w, a22b);
    k_agg<<<NN, 128>>>(hth, b2, hh, 0);           // hh = h2, fp16

    // ---- collator + classifier ----
    k_gemm<1><<<gg, 256>>>(hh, Wc, hth, NN, bc, 1);   // hth = feat, fp16
    k_cls<<<(NN + 7) / 8, 256>>>(hth, Wcls, bcls, out);
}

// round 6
// speedup vs baseline: 2.5183x; 1.2222x over previous
#include <cuda_runtime.h>
#include <cuda_fp16.h>
#include <math.h>
#include <stdint.h>

#define NN 100000
#define EE 1600000
#define HH 4
#define HIDD 64
#define FD 256   // H*HID == IN == FC

// ---------------- scratch (device globals; no allocations anywhere) ----------
__device__ __half g_hth[(size_t)NN * FD];  // GEMM outputs (ht / feat), fp16
__device__ __half g_hh [(size_t)NN * FD];  // agg outputs (h1 / h2), fp16
__device__ float  g_a1[HH * NN];
__device__ float  g_a2[HH * NN];
__device__ int    g_cnt[NN];
__device__ int    g_cur[NN];
__device__ int    g_incl[NN];
__device__ int    g_rowptr[NN + 1];
__device__ int    g_bsum[128];
__device__ int    g_boff[128];
__device__ int    g_sdst[EE];

// ---------------- CSR build ---------------------------------------------------
__global__ void k_zero_counts() {
    int i = blockIdx.x * blockDim.x + threadIdx.x;
    if (i < NN) { g_cnt[i] = 0; g_cur[i] = 0; }
}

__global__ void k_hist(const int* __restrict__ src) {
    int e = blockIdx.x * blockDim.x + threadIdx.x;
    if (e < EE) atomicAdd(&g_cnt[src[e]], 1);
}

__global__ void k_scan_block() {
    __shared__ int sh[1024];
    int tid = threadIdx.x;
    int i = blockIdx.x * 1024 + tid;
    int v = (i < NN) ? g_cnt[i] : 0;
    sh[tid] = v;
    __syncthreads();
    for (int off = 1; off < 1024; off <<= 1) {
        int t = (tid >= off) ? sh[tid - off] : 0;
        __syncthreads();
        sh[tid] += t;
        __syncthreads();
    }
    if (i < NN) g_incl[i] = sh[tid];
    if (tid == 1023) g_bsum[blockIdx.x] = sh[1023];
}

__global__ void k_scan_top2(int nb) {
    __shared__ int ws[4];
    int t = threadIdx.x;
    int lane = t & 31, w = t >> 5;
    int v = (t < nb) ? g_bsum[t] : 0;
    int s = v;
#pragma unroll
    for (int off = 1; off < 32; off <<= 1) {
        int u = __shfl_up_sync(0xffffffffu, s, off);
        if (lane >= off) s += u;
    }
    if (lane == 31) ws[w] = s;
    __syncthreads();
    int add = 0;
#pragma unroll
    for (int i = 0; i < 4; i++) if (i < w) add += ws[i];
    if (t < nb) g_boff[t] = add + s - v;
}

__global__ void k_rowptr() {
    int i = blockIdx.x * blockDim.x + threadIdx.x;
    if (i < NN) g_rowptr[i] = g_boff[i >> 10] + g_incl[i] - g_cnt[i];
    if (i == 0) g_rowptr[NN] = EE;
}

__global__ void k_scatter(const int* __restrict__ src, const int* __restrict__ dst) {
    int e = blockIdx.x * blockDim.x + threadIdx.x;
    if (e >= EE) return;
    int u = src[e];
    int pos = g_rowptr[u] + atomicAdd(&g_cur[u], 1);
    g_sdst[pos] = dst[e];
}

// ---------------- fp16 tensor-core GEMM (ldmatrix + m16n8k16) ------------------
// C[M,256] = A[M,256] * B[256,256]^T; A fp32 or fp16 (template), C fp16.
// Block 128x128, BK=32 halves (64B rows, SW64 swizzle), 8 warps of 64x32.
#define TILE_BYTES 8192   // 128 rows * 64 B

__device__ __forceinline__ uint32_t sw64(uint32_t o) { return o ^ ((o >> 3) & 0x30); }

__device__ __forceinline__ uint32_t pack2(float x, float y) {
    __half2 h = __floats2half2_rn(x, y);
    return *(uint32_t*)&h;
}

__device__ __forceinline__ void ldsm4(uint32_t& r0, uint32_t& r1, uint32_t& r2, uint32_t& r3,
                                      uint32_t addr) {
    asm volatile("ldmatrix.sync.aligned.m8n8.x4.shared.b16 {%0,%1,%2,%3}, [%4];"
                 : "=r"(r0), "=r"(r1), "=r"(r2), "=r"(r3) : "r"(addr));
}

__device__ __forceinline__ void mma_f16(float& d0, float& d1, float& d2, float& d3,
                                        uint32_t a0, uint32_t a1, uint32_t a2, uint32_t a3,
                                        uint32_t b0, uint32_t b1) {
    asm volatile(
        "mma.sync.aligned.m16n8k16.row.col.f32.f16.f16.f32 "
        "{%0,%1,%2,%3}, {%4,%5,%6,%7}, {%8,%9}, {%0,%1,%2,%3};\n"
        : "+f"(d0), "+f"(d1), "+f"(d2), "+f"(d3)
        : "r"(a0), "r"(a1), "r"(a2), "r"(a3), "r"(b0), "r"(b1));
}

template<int AHALF>
__global__ __launch_bounds__(256, 2)
void k_gemm(const void* __restrict__ Ain, const float* __restrict__ B,
            __half* __restrict__ Ch, int M,
            const float* __restrict__ bias, int relu) {
    const int K = 256;
    __shared__ __align__(128) unsigned char AS[2][TILE_BYTES];
    __shared__ __align__(128) unsigned char BS[2][TILE_BYTES];

    const float*  Af = (const float*)Ain;
    const __half* Ah = (const __half*)Ain;

    int tid  = threadIdx.x;
    int row0 = blockIdx.y * 128;
    int col0 = blockIdx.x * 128;
    int warp = tid >> 5, lane = tid & 31;
    int wm = (warp & 1) * 64;
    int wn = (warp >> 1) * 32;

    int lr   = tid >> 1;      // 0..127 (tile row)
    int cseg = tid & 1;       // which 32B half-row

    bool aok = (row0 + lr) < M;
    size_t aoff = (size_t)(row0 + lr) * K + cseg * 16;   // element offset
    const float* bptr = B + (size_t)(col0 + lr) * K + cseg * 16;

    uint32_t as_base = (uint32_t)__cvta_generic_to_shared(AS);
    uint32_t bs_base = (uint32_t)__cvta_generic_to_shared(BS);
    uint32_t st_off0 = sw64((uint32_t)(lr * 64 + cseg * 32));
    uint32_t st_off1 = sw64((uint32_t)(lr * 64 + cseg * 32 + 16));

    uint4 pa0, pa1, pb0, pb1;
    const uint4 z4 = make_uint4(0u, 0u, 0u, 0u);

    auto ldA = [&](int kt) {
        if (!aok) { pa0 = z4; pa1 = z4; return; }
        if (AHALF) {
            const uint4* p = (const uint4*)(Ah + aoff + kt * 32);
            pa0 = p[0]; pa1 = p[1];
        } else {
            const float4* p = (const float4*)(Af + aoff + kt * 32);
            float4 f0 = p[0], f1 = p[1], f2 = p[2], f3 = p[3];
            pa0 = make_uint4(pack2(f0.x, f0.y), pack2(f0.z, f0.w),
                             pack2(f1.x, f1.y), pack2(f1.z, f1.w));
            pa1 = make_uint4(pack2(f2.x, f2.y), pack2(f2.z, f2.w),
                             pack2(f3.x, f3.y), pack2(f3.z, f3.w));
        }
    };
    auto ldB = [&](int kt) {
        const float4* p = (const float4*)(bptr + kt * 32);
        float4 f0 = p[0], f1 = p[1], f2 = p[2], f3 = p[3];
        pb0 = make_uint4(pack2(f0.x, f0.y), pack2(f0.z, f0.w),
                         pack2(f1.x, f1.y), pack2(f1.z, f1.w));
        pb1 = make_uint4(pack2(f2.x, f2.y), pack2(f2.z, f2.w),
                         pack2(f3.x, f3.y), pack2(f3.z, f3.w));
    };
    auto store = [&](int buf) {
        *(uint4*)(AS[buf] + st_off0) = pa0;
        *(uint4*)(AS[buf] + st_off1) = pa1;
        *(uint4*)(BS[buf] + st_off0) = pb0;
        *(uint4*)(BS[buf] + st_off1) = pb1;
    };

    float acc[4][4][4];
#pragma unroll
    for (int i = 0; i < 4; i++)
#pragma unroll
        for (int j = 0; j < 4; j++)
#pragma unroll
            for (int c = 0; c < 4; c++) acc[i][j][c] = 0.f;

    // ldmatrix lane addressing (byte offsets within a tile buffer)
    uint32_t a_row = (uint32_t)(lane & 15);        // row within 16-row m-tile
    uint32_t a_kh  = (uint32_t)(lane >> 4);        // k-half (16B chunk) select
    uint32_t b_n   = (uint32_t)((lane & 7) + ((lane >> 4) & 1) * 8);
    uint32_t b_kh  = (uint32_t)((lane >> 3) & 1);

    ldA(0); ldB(0);
    store(0);
    __syncthreads();

    const int NIT = K / 32;   // 8
    for (int kt = 0; kt < NIT; kt++) {
        int buf = kt & 1;
        if (kt + 1 < NIT) { ldA(kt + 1); ldB(kt + 1); }

        uint32_t abase = as_base + buf * TILE_BYTES;
        uint32_t bbase = bs_base + buf * TILE_BYTES;

#pragma unroll
        for (int ks = 0; ks < 2; ks++) {
            uint32_t af[4][4];
#pragma unroll
            for (int mt = 0; mt < 4; mt++) {
                uint32_t off = (wm + mt * 16 + a_row) * 64 + (ks * 2 + a_kh) * 16;
                ldsm4(af[mt][0], af[mt][1], af[mt][2], af[mt][3], abase + sw64(off));
            }
            uint32_t bfr[2][4];
#pragma unroll
            for (int bt = 0; bt < 2; bt++) {
                uint32_t off = (wn + bt * 16 + b_n) * 64 + (ks * 2 + b_kh) * 16;
                ldsm4(bfr[bt][0], bfr[bt][1], bfr[bt][2], bfr[bt][3], bbase + sw64(off));
            }
#pragma unroll
            for (int mt = 0; mt < 4; mt++)
#pragma unroll
                for (int nt = 0; nt < 4; nt++) {
                    uint32_t b0 = bfr[nt >> 1][(nt & 1) * 2];
                    uint32_t b1 = bfr[nt >> 1][(nt & 1) * 2 + 1];
                    mma_f16(acc[mt][nt][0], acc[mt][nt][1], acc[mt][nt][2], acc[mt][nt][3],
                            af[mt][0], af[mt][1], af[mt][2], af[mt][3], b0, b1);
                }
        }

        if (kt + 1 < NIT) store(buf ^ 1);
        __syncthreads();
    }

    // epilogue: rows r, r+8 within each 16-row m-tile; cols 2c, 2c+1 per 8-col n-tile
    int r = lane >> 2;
    int c = lane & 3;
#pragma unroll
    for (int mt = 0; mt < 4; mt++) {
#pragma unroll
        for (int nt = 0; nt < 4; nt++) {
            int col = col0 + wn + nt * 8 + c * 2;
            float bx = 0.f, by = 0.f;
            if (bias) { bx = bias[col]; by = bias[col + 1]; }
            int row_a = row0 + wm + mt * 16 + r;
            int row_b = row_a + 8;
            float v0 = acc[mt][nt][0] + bx, v1 = acc[mt][nt][1] + by;
            float v2 = acc[mt][nt][2] + bx, v3 = acc[mt][nt][3] + by;
            if (relu) {
                v0 = fmaxf(v0, 0.f); v1 = fmaxf(v1, 0.f);
                v2 = fmaxf(v2, 0.f); v3 = fmaxf(v3, 0.f);
            }
            if (row_a < M) *(__half2*)&Ch[(size_t)row_a * 256 + col] = __floats2half2_rn(v0, v1);
            if (row_b < M) *(__half2*)&Ch[(size_t)row_b * 256 + col] = __floats2half2_rn(v2, v3);
        }
    }
}

// ---------------- per-node attention scalars (fp16 input) ---------------------
__global__ void k_scores(const __half* __restrict__ ht,
                         const float* __restrict__ a1w, const float* __restrict__ a1b,
                         const float* __restrict__ a2w, const float* __restrict__ a2b) {
    int gw = (blockIdx.x * blockDim.x + threadIdx.x) >> 5;
    int lane = threadIdx.x & 31;
    if (gw >= NN * HH) return;
    int i = gw & 3;
    int n = gw >> 2;
    const __half2* hr = (const __half2*)(ht + (size_t)n * FD + i * HIDD);
    float2 v = __half22float2(hr[lane]);
    int ch = i * HIDD + 2 * lane;
    float p1 = v.x * a1w[ch] + v.y * a1w[ch + 1];
    float p2 = v.x * a2w[ch] + v.y * a2w[ch + 1];
#pragma unroll
    for (int off = 16; off; off >>= 1) {
        p1 += __shfl_down_sync(0xffffffffu, p1, off);
        p2 += __shfl_down_sync(0xffffffffu, p2, off);
    }
    if (lane == 0) {
        g_a1[i * NN + n] = p1 + a1b[i];
        g_a2[i * NN + n] = p2 + a2b[i];
    }
}

// ---------------- fused edge softmax + aggregation (fp16 in/out) --------------
__global__ __launch_bounds__(128, 8)
void k_agg(const __half* __restrict__ hth, const float* __restrict__ b,
           __half* __restrict__ out, int relu) {
    int n = blockIdx.x;
    int i = threadIdx.x >> 5;
    int lane = threadIdx.x & 31;
    int s0 = g_rowptr[n], s1 = g_rowptr[n + 1];
    float a1u = g_a1[i * NN + n];
    const float* a2p = g_a2 + (size_t)i * NN;

    float acc0 = 0.f, acc1 = 0.f, den = 0.f;

    for (int base = s0; base < s1; base += 32) {
        int m = s1 - base;
        int cnt = m < 32 ? m : 32;
        int d = 0; float w = 0.f;
        if (lane < cnt) {
            d = g_sdst[base + lane];
            float z = a1u + a2p[d];
            z = z > 0.f ? z : 0.2f * z;
            w = __expf(z);
        }
        for (int j = 0; j < cnt; j++) {
            float wj = __shfl_sync(0xffffffffu, w, j);
            int   dj = __shfl_sync(0xffffffffu, d, j);
            const __half2* hr = (const __half2*)(hth + (size_t)dj * FD + i * HIDD);
            float2 vf = __half22float2(hr[lane]);
            den  += wj;
            acc0 += wj * vf.x;
            acc1 += wj * vf.y;
        }
    }

    float inv = 1.f / den;
    int ch = i * HIDD + 2 * lane;
    float o0 = acc0 * inv + b[ch];
    float o1 = acc1 * inv + b[ch + 1];
    if (relu) { o0 = fmaxf(o0, 0.f); o1 = fmaxf(o1, 0.f); }
    *(__half2*)&out[(size_t)n * FD + ch] = __floats2half2_rn(o0, o1);
}

// ---------------- classifier: [N,256](fp16) x [4,256]^T + bias ----------------
__global__ void k_cls(const __half* __restrict__ feat, const float* __restrict__ W,
                      const float* __restrict__ bias, float* __restrict__ out) {
    __shared__ float w[1024];
    int tid = threadIdx.x;
#pragma unroll
    for (int j = 0; j < 4; j++) w[tid + 256 * j] = W[tid + 256 * j];
    __syncthreads();
    int warp = tid >> 5, lane = tid & 31;
    int n = blockIdx.x * 8 + warp;
    if (n >= NN) return;
    const __half2* f = (const __half2*)(feat + (size_t)n * 256);
    float p0 = 0.f, p1 = 0.f, p2 = 0.f, p3 = 0.f;
#pragma unroll
    for (int k = lane; k < 128; k += 32) {
        float2 x = __half22float2(f[k]);
        int c0 = 2 * k, c1 = 2 * k + 1;
        p0 += x.x * w[c0]       + x.y * w[c1];
        p1 += x.x * w[256 + c0] + x.y * w[256 + c1];
        p2 += x.x * w[512 + c0] + x.y * w[512 + c1];
        p3 += x.x * w[768 + c0] + x.y * w[768 + c1];
    }
#pragma unroll
    for (int off = 16; off; off >>= 1) {
        p0 += __shfl_down_sync(0xffffffffu, p0, off);
        p1 += __shfl_down_sync(0xffffffffu, p1, off);
        p2 += __shfl_down_sync(0xffffffffu, p2, off);
        p3 += __shfl_down_sync(0xffffffffu, p3, off);
    }
    if (lane == 0) {
        out[(size_t)n * 4 + 0] = p0 + bias[0];
        out[(size_t)n * 4 + 1] = p1 + bias[1];
        out[(size_t)n * 4 + 2] = p2 + bias[2];
        out[(size_t)n * 4 + 3] = p3 + bias[3];
    }
}

// ---------------- launch -------------------------------------------------------
extern "C" void kernel_launch(void* const* d_in, const int* in_sizes, int n_in,
                              void* d_out, int out_size) {
    const float* x    = (const float*)d_in[0];
    const int*   ei   = (const int*)  d_in[1];
    const float* W1   = (const float*)d_in[2];
    const float* a11w = (const float*)d_in[3];
    const float* a11b = (const float*)d_in[4];
    const float* a12w = (const float*)d_in[5];
    const float* a12b = (const float*)d_in[6];
    const float* b1   = (const float*)d_in[7];
    const float* W2   = (const float*)d_in[8];
    const float* a21w = (const float*)d_in[9];
    const float* a21b = (const float*)d_in[10];
    const float* a22w = (const float*)d_in[11];
    const float* a22b = (const float*)d_in[12];
    const float* b2   = (const float*)d_in[13];
    const float* Wc   = (const float*)d_in[14];
    const float* bc   = (const float*)d_in[15];
    const float* Wcls = (const float*)d_in[16];
    const float* bcls = (const float*)d_in[17];
    float* out = (float*)d_out;

    const int* srcp = ei;
    const int* dstp = ei + EE;

    __half *hth = nullptr, *hh = nullptr;
    cudaGetSymbolAddress((void**)&hth, g_hth);
    cudaGetSymbolAddress((void**)&hh,  g_hh);

    int tE = (EE + 255) / 256;
    int tN = (NN + 255) / 256;
    int nScanBlocks = (NN + 1023) / 1024;

    dim3 gg(2, (NN + 127) / 128);
    int scoreBlocks = (NN * HH + 7) / 8;

    // CSR build interleaved with GEMM1; GEMM1 stays in the profiled slot.
    k_zero_counts<<<tN, 256>>>();
    k_hist<<<tE, 256>>>(srcp);
    k_scan_block<<<nScanBlocks, 1024>>>();
    k_gemm<0><<<gg, 256>>>(x, W1, hth, NN, nullptr, 0);       // profiled slot
    k_scan_top2<<<1, 128>>>(nScanBlocks);
    k_rowptr<<<tN, 256>>>();
    k_scatter<<<tE, 256>>>(srcp, dstp);

    // ---- layer 1 ----
    k_scores<<<scoreBlocks, 256>>>(hth, a11w, a11b, a12w, a12b);
    k_agg<<<NN, 128>>>(hth, b1, hh, 1);           // hh = relu(h1), fp16

    // ---- layer 2 ----
    k_gemm<1><<<gg, 256>>>(hh, W2, hth, NN, nullptr, 0);
    k_scores<<<scoreBlocks, 256>>>(hth, a21w, a21b, a22w, a22b);
    k_agg<<<NN, 128>>>(hth, b2, hh, 0);           // hh = h2, fp16

    // ---- collator + classifier ----
    k_gemm<1><<<gg, 256>>>(hh, Wc, hth, NN, bc, 1);   // hth = feat, fp16
    k_cls<<<(NN + 7) / 8, 256>>>(hth, Wcls, bcls, out);
}